// round 5
// baseline (speedup 1.0000x reference)
#include <cuda_runtime.h>
#include <math.h>
#include <stdint.h>

#define N_NODES 30000
#define E_EDGES 480000
#define G_DIM   256
#define ATT_SCALE 0.0625f   /* 256^-0.5 */
#define LN_EPS  1e-5f

// ---------------- device scratch (static allocation only) ----------------
__device__ float g_mu[N_NODES];
__device__ float g_rs[N_NODES];
__device__ float g_q[N_NODES * G_DIM];
__device__ float g_k[N_NODES * G_DIM];
__device__ float g_v[N_NODES * G_DIM];
__device__ int   g_deg[N_NODES];
__device__ int   g_cur[N_NODES];
__device__ int   g_off[N_NODES + 1];
__device__ int   g_csr_src[E_EDGES];

// ---------------- LayerNorm row stats (also zeroes g_deg) ----------------
__global__ void ln_stats_kernel(const float* __restrict__ s) {
    int gtid = blockIdx.x * blockDim.x + threadIdx.x;
    if (gtid < N_NODES) g_deg[gtid] = 0;     // fused zero for histogram
    int warp = gtid >> 5;
    if (warp >= N_NODES) return;
    int lane = threadIdx.x & 31;
    const float4* p = (const float4*)(s + (size_t)warp * G_DIM);
    float sum = 0.f, sq = 0.f;
    #pragma unroll
    for (int i = lane; i < 64; i += 32) {
        float4 f = p[i];
        sum += f.x + f.y + f.z + f.w;
        sq  += f.x * f.x + f.y * f.y + f.z * f.z + f.w * f.w;
    }
    #pragma unroll
    for (int o = 16; o > 0; o >>= 1) {
        sum += __shfl_xor_sync(0xffffffffu, sum, o);
        sq  += __shfl_xor_sync(0xffffffffu, sq, o);
    }
    if (lane == 0) {
        float mu  = sum * (1.f / G_DIM);
        float var = sq * (1.f / G_DIM) - mu * mu;
        g_mu[warp] = mu;
        g_rs[warp] = rsqrtf(var + LN_EPS);
    }
}

// ---------------- tf32 helpers ----------------
__device__ __forceinline__ uint32_t to_tf32(float x) {
    uint32_t t;
    asm("cvt.rna.tf32.f32 %0, %1;" : "=r"(t) : "f"(x));
    return t;
}

__device__ __forceinline__ void mma_tf32(float c[4], const uint32_t a[4], const uint32_t b[2]) {
    asm volatile(
        "mma.sync.aligned.m16n8k8.row.col.f32.tf32.tf32.f32 "
        "{%0,%1,%2,%3}, {%4,%5,%6,%7}, {%8,%9}, {%0,%1,%2,%3};"
        : "+f"(c[0]), "+f"(c[1]), "+f"(c[2]), "+f"(c[3])
        : "r"(a[0]), "r"(a[1]), "r"(a[2]), "r"(a[3]), "r"(b[0]), "r"(b[1]));
}

// ---------------- fused LN-apply + QKV GEMM (tf32 tensor cores) ----------------
__global__ __launch_bounds__(256) void qkv_gemm_tf32_kernel(
    const float* __restrict__ s, const float* __restrict__ W,
    const float* __restrict__ gamma, const float* __restrict__ beta) {

    __shared__ uint32_t Asm[4][8][32][4];   // 16 KB
    __shared__ uint32_t Bsm[4][8][32][2];   // 8 KB

    int tid  = threadIdx.x;
    int warp = tid >> 5;
    int lane = tid & 31;
    int wm = warp >> 1;      // 0..3  (M)
    int wn = warp & 1;       // 0..1  (N)
    int bm = blockIdx.y * 128;
    int bn = blockIdx.x * 64;

    float acc[2][4][4];
    #pragma unroll
    for (int mi = 0; mi < 2; mi++)
        #pragma unroll
        for (int ni = 0; ni < 4; ni++)
            #pragma unroll
            for (int r = 0; r < 4; r++) acc[mi][ni][r] = 0.f;

    for (int kt = 0; kt < G_DIM; kt += 32) {
        #pragma unroll
        for (int i = 0; i < 4; i++) {
            int idx = tid + i * 256;
            int r   = idx >> 3;
            int c4  = (idx & 7) * 4;
            int gr  = bm + r;
            float4 f = make_float4(0.f, 0.f, 0.f, 0.f);
            if (gr < N_NODES) {
                f = *(const float4*)(s + (size_t)gr * G_DIM + kt + c4);
                float mu = g_mu[gr], rs = g_rs[gr];
                f.x = (f.x - mu) * rs * __ldg(&gamma[kt + c4 + 0]) + __ldg(&beta[kt + c4 + 0]);
                f.y = (f.y - mu) * rs * __ldg(&gamma[kt + c4 + 1]) + __ldg(&beta[kt + c4 + 1]);
                f.z = (f.z - mu) * rs * __ldg(&gamma[kt + c4 + 2]) + __ldg(&beta[kt + c4 + 2]);
                f.w = (f.w - mu) * rs * __ldg(&gamma[kt + c4 + 3]) + __ldg(&beta[kt + c4 + 3]);
            }
            float fv[4] = {f.x, f.y, f.z, f.w};
            int mi = r >> 4, rr = r & 15;
            #pragma unroll
            for (int j = 0; j < 4; j++) {
                int col = c4 + j;
                int ks = col >> 3, cc = col & 7;
                int lt = (rr & 7) * 4 + (cc & 3);
                int rg = ((rr >> 3) & 1) | ((cc >> 2) << 1);
                Asm[ks][mi][lt][rg] = to_tf32(fv[j]);
            }
        }
        #pragma unroll
        for (int i = 0; i < 2; i++) {
            int idx = tid + i * 256;
            int r   = idx >> 4;
            int c4  = (idx & 15) * 4;
            float4 f = *(const float4*)(W + (size_t)(kt + r) * 768 + bn + c4);
            float fv[4] = {f.x, f.y, f.z, f.w};
            int ks = r >> 3, kk = r & 7;
            #pragma unroll
            for (int j = 0; j < 4; j++) {
                int col = c4 + j;
                int ni = col >> 3, nn = col & 7;
                int lt = nn * 4 + (kk & 3);
                int rg = kk >> 2;
                Bsm[ks][ni][lt][rg] = to_tf32(fv[j]);
            }
        }
        __syncthreads();

        #pragma unroll
        for (int ks = 0; ks < 4; ks++) {
            uint32_t a[2][4];
            #pragma unroll
            for (int mi = 0; mi < 2; mi++)
                *(uint4*)a[mi] = *(const uint4*)&Asm[ks][wm * 2 + mi][lane][0];
            uint32_t b[4][2];
            #pragma unroll
            for (int ni = 0; ni < 4; ni++)
                *(uint2*)b[ni] = *(const uint2*)&Bsm[ks][wn * 4 + ni][lane][0];
            #pragma unroll
            for (int mi = 0; mi < 2; mi++)
                #pragma unroll
                for (int ni = 0; ni < 4; ni++)
                    mma_tf32(acc[mi][ni], a[mi], b[ni]);
        }
        __syncthreads();
    }

    int third = bn >> 8;
    float* outp = (third == 0) ? g_q : (third == 1) ? g_k : g_v;
    int lc_base = (bn & 255) + wn * 32;
    int gid = lane >> 2, tig = lane & 3;
    #pragma unroll
    for (int mi = 0; mi < 2; mi++) {
        int row0 = bm + wm * 32 + mi * 16 + gid;
        #pragma unroll
        for (int ni = 0; ni < 4; ni++) {
            int col = lc_base + ni * 8 + tig * 2;
            if (row0 < N_NODES)
                *(float2*)&outp[(size_t)row0 * G_DIM + col] =
                    make_float2(acc[mi][ni][0], acc[mi][ni][1]);
            if (row0 + 8 < N_NODES)
                *(float2*)&outp[(size_t)(row0 + 8) * G_DIM + col] =
                    make_float2(acc[mi][ni][2], acc[mi][ni][3]);
        }
    }
}

// ---------------- CSR build ----------------
__global__ void hist_kernel(const int* __restrict__ dst) {
    int e = blockIdx.x * blockDim.x + threadIdx.x;
    if (e < E_EDGES) atomicAdd(&g_deg[dst[e]], 1);
}

__global__ void scan_kernel() {
    __shared__ int part[1024];
    const int PER = 30;   // 1024*30 >= 30000
    int t = threadIdx.x;
    int beg = t * PER;
    int end = min(N_NODES, beg + PER);
    int sum = 0;
    for (int i = beg; i < end; i++) sum += g_deg[i];
    part[t] = sum;
    __syncthreads();
    if (t == 0) {
        int run = 0;
        for (int i = 0; i < 1024; i++) { int v = part[i]; part[i] = run; run += v; }
    }
    __syncthreads();
    int run = part[t];
    for (int i = beg; i < end; i++) { g_off[i] = run; run += g_deg[i]; g_cur[i] = 0; }
    if (end == N_NODES && beg < N_NODES) g_off[N_NODES] = run;
}

__global__ void scatter_kernel(const int* __restrict__ src, const int* __restrict__ dst) {
    int e = blockIdx.x * blockDim.x + threadIdx.x;
    if (e >= E_EDGES) return;
    int d = dst[e];
    int pos = atomicAdd(&g_cur[d], 1);
    g_csr_src[g_off[d] + pos] = src[e];
}

// ---------------- per-node attention, one warp per dst node ----------------
// 4-edge software pipeline: batch 4 CSR indices, issue all 16 LDG.128 up
// front (MLP=16), then compute. Flips the loop from L2-latency-bound to
// L2-throughput-bound. Logits q*k*2^-4 are tiny -> plain exp == softmax.
__global__ __launch_bounds__(128) void attn_kernel(float* __restrict__ out) {
    int node = (blockIdx.x * blockDim.x + threadIdx.x) >> 5;
    if (node >= N_NODES) return;
    int lane = threadIdx.x & 31;

    const float4* kp = (const float4*)(g_k + (size_t)node * G_DIM);
    float4 k0 = kp[lane * 2];
    float4 k1 = kp[lane * 2 + 1];
    float kk[8] = {k0.x * ATT_SCALE, k0.y * ATT_SCALE, k0.z * ATT_SCALE, k0.w * ATT_SCALE,
                   k1.x * ATT_SCALE, k1.y * ATT_SCALE, k1.z * ATT_SCALE, k1.w * ATT_SCALE};

    float z[8], a[8];
    #pragma unroll
    for (int d = 0; d < 8; d++) { z[d] = 0.f; a[d] = 0.f; }

    int e   = g_off[node];
    int end = g_off[node + 1];

    for (; e + 4 <= end; e += 4) {
        int sn[4];
        #pragma unroll
        for (int j = 0; j < 4; j++) sn[j] = g_csr_src[e + j];

        float4 q0[4], q1[4], v0[4], v1[4];
        #pragma unroll
        for (int j = 0; j < 4; j++) {
            const float4* qp = (const float4*)(g_q + (size_t)sn[j] * G_DIM) + lane * 2;
            const float4* vp = (const float4*)(g_v + (size_t)sn[j] * G_DIM) + lane * 2;
            q0[j] = qp[0]; q1[j] = qp[1];
            v0[j] = vp[0]; v1[j] = vp[1];
        }
        #pragma unroll
        for (int j = 0; j < 4; j++) {
            float qa[8] = {q0[j].x, q0[j].y, q0[j].z, q0[j].w,
                           q1[j].x, q1[j].y, q1[j].z, q1[j].w};
            float va[8] = {v0[j].x, v0[j].y, v0[j].z, v0[j].w,
                           v1[j].x, v1[j].y, v1[j].z, v1[j].w};
            #pragma unroll
            for (int d = 0; d < 8; d++) {
                float p = __expf(qa[d] * kk[d]);
                z[d] += p;
                a[d] = fmaf(p, va[d], a[d]);
            }
        }
    }
    for (; e < end; e++) {
        int sN = g_csr_src[e];
        const float4* qp = (const float4*)(g_q + (size_t)sN * G_DIM) + lane * 2;
        const float4* vp = (const float4*)(g_v + (size_t)sN * G_DIM) + lane * 2;
        float4 q0 = qp[0], q1 = qp[1];
        float4 v0 = vp[0], v1 = vp[1];
        float qa[8] = {q0.x, q0.y, q0.z, q0.w, q1.x, q1.y, q1.z, q1.w};
        float va[8] = {v0.x, v0.y, v0.z, v0.w, v1.x, v1.y, v1.z, v1.w};
        #pragma unroll
        for (int d = 0; d < 8; d++) {
            float p = __expf(qa[d] * kk[d]);
            z[d] += p;
            a[d] = fmaf(p, va[d], a[d]);
        }
    }

    float res[8];
    #pragma unroll
    for (int d = 0; d < 8; d++) res[d] = (z[d] > 0.f) ? a[d] / z[d] : 0.f;
    float4* op = (float4*)(out + (size_t)node * G_DIM);
    op[lane * 2]     = make_float4(res[0], res[1], res[2], res[3]);
    op[lane * 2 + 1] = make_float4(res[4], res[5], res[6], res[7]);
}

// ---------------- launch ----------------
extern "C" void kernel_launch(void* const* d_in, const int* in_sizes, int n_in,
                              void* d_out, int out_size) {
    const float* s     = (const float*)d_in[0];
    const float* Wqkv  = (const float*)d_in[1];
    const float* gamma = (const float*)d_in[2];
    const float* beta  = (const float*)d_in[3];
    const int*   src   = (const int*)d_in[4];
    const int*   dst   = (const int*)d_in[5];
    float* out = (float*)d_out;

    ln_stats_kernel<<<(N_NODES * 32 + 255) / 256, 256>>>(s);

    hist_kernel<<<(E_EDGES + 255) / 256, 256>>>(dst);

    dim3 gemm_grid(768 / 64, (N_NODES + 127) / 128);
    qkv_gemm_tf32_kernel<<<gemm_grid, 256>>>(s, Wqkv, gamma, beta);

    scan_kernel<<<1, 1024>>>();
    scatter_kernel<<<(E_EDGES + 255) / 256, 256>>>(src, dst);

    // one warp per node: N_NODES * 32 threads total
    attn_kernel<<<(N_NODES * 32 + 127) / 128, 128>>>(out);
}

// round 6
// speedup vs baseline: 1.1485x; 1.1485x over previous
#include <cuda_runtime.h>
#include <math.h>
#include <stdint.h>

#define N_NODES 30000
#define E_EDGES 480000
#define G_DIM   256
#define ATT_SCALE 0.0625f   /* 256^-0.5 */
#define LN_EPS  1e-5f

// ---------------- device scratch (static allocation only) ----------------
__device__ float g_x[N_NODES * G_DIM];   // normalized input
__device__ float g_q[N_NODES * G_DIM];
__device__ float g_k[N_NODES * G_DIM];
__device__ float g_v[N_NODES * G_DIM];
__device__ int   g_deg[N_NODES];
__device__ int   g_cur[N_NODES];
__device__ int   g_off[N_NODES + 1];
__device__ int   g_csr_src[E_EDGES];

// ---------------- LayerNorm (stats + apply), one warp per row; zeroes g_deg ----------------
__global__ void ln_kernel(const float* __restrict__ s,
                          const float* __restrict__ gamma,
                          const float* __restrict__ beta) {
    int gtid = blockIdx.x * blockDim.x + threadIdx.x;
    if (gtid < N_NODES) g_deg[gtid] = 0;     // fused zero for histogram
    int row = gtid >> 5;
    if (row >= N_NODES) return;
    int lane = threadIdx.x & 31;

    const float4* p = (const float4*)(s + (size_t)row * G_DIM);
    float4 f0 = p[lane];
    float4 f1 = p[lane + 32];
    float sum = f0.x + f0.y + f0.z + f0.w + f1.x + f1.y + f1.z + f1.w;
    float sq  = f0.x*f0.x + f0.y*f0.y + f0.z*f0.z + f0.w*f0.w
              + f1.x*f1.x + f1.y*f1.y + f1.z*f1.z + f1.w*f1.w;
    #pragma unroll
    for (int o = 16; o > 0; o >>= 1) {
        sum += __shfl_xor_sync(0xffffffffu, sum, o);
        sq  += __shfl_xor_sync(0xffffffffu, sq, o);
    }
    float mu = sum * (1.f / G_DIM);
    float rs = rsqrtf(sq * (1.f / G_DIM) - mu * mu + LN_EPS);

    float4 ga = ((const float4*)gamma)[lane];
    float4 gb = ((const float4*)gamma)[lane + 32];
    float4 ba = ((const float4*)beta)[lane];
    float4 bb = ((const float4*)beta)[lane + 32];
    float4 o0, o1;
    o0.x = (f0.x - mu) * rs * ga.x + ba.x;
    o0.y = (f0.y - mu) * rs * ga.y + ba.y;
    o0.z = (f0.z - mu) * rs * ga.z + ba.z;
    o0.w = (f0.w - mu) * rs * ga.w + ba.w;
    o1.x = (f1.x - mu) * rs * gb.x + bb.x;
    o1.y = (f1.y - mu) * rs * gb.y + bb.y;
    o1.z = (f1.z - mu) * rs * gb.z + bb.z;
    o1.w = (f1.w - mu) * rs * gb.w + bb.w;
    float4* op = (float4*)(g_x + (size_t)row * G_DIM);
    op[lane]      = o0;
    op[lane + 32] = o1;
}

// ---------------- tf32 helpers ----------------
__device__ __forceinline__ uint32_t to_tf32(float x) {
    uint32_t t;
    asm("cvt.rna.tf32.f32 %0, %1;" : "=r"(t) : "f"(x));
    return t;
}

__device__ __forceinline__ void mma_tf32(float c[4], const uint32_t a[4], const uint32_t b[2]) {
    asm volatile(
        "mma.sync.aligned.m16n8k8.row.col.f32.tf32.tf32.f32 "
        "{%0,%1,%2,%3}, {%4,%5,%6,%7}, {%8,%9}, {%0,%1,%2,%3};"
        : "+f"(c[0]), "+f"(c[1]), "+f"(c[2]), "+f"(c[3])
        : "r"(a[0]), "r"(a[1]), "r"(a[2]), "r"(a[3]), "r"(b[0]), "r"(b[1]));
}

// ---------------- QKV GEMM (tf32 tensor cores, register-prefetch pipelined) ----------------
// C[N,768] = X[N,256] @ W[256,768]; block tile 128x64, K-chunk 32, 8 warps (4Mx2N).
__global__ __launch_bounds__(256) void qkv_gemm_tf32_kernel(
    const float* __restrict__ W) {

    __shared__ uint32_t Asm[4][8][32][4];   // 16 KB
    __shared__ uint32_t Bsm[4][8][32][2];   // 8 KB

    int tid  = threadIdx.x;
    int warp = tid >> 5;
    int lane = tid & 31;
    int wm = warp >> 1;
    int wn = warp & 1;
    int bm = blockIdx.y * 128;
    int bn = blockIdx.x * 64;

    float acc[2][4][4];
    #pragma unroll
    for (int mi = 0; mi < 2; mi++)
        #pragma unroll
        for (int ni = 0; ni < 4; ni++)
            #pragma unroll
            for (int r = 0; r < 4; r++) acc[mi][ni][r] = 0.f;

    // per-thread load coordinates
    int ar[4], ac4[4];
    #pragma unroll
    for (int i = 0; i < 4; i++) {
        int idx = tid + i * 256;
        ar[i]  = idx >> 3;
        ac4[i] = (idx & 7) * 4;
    }
    int br[2], bc4[2];
    #pragma unroll
    for (int i = 0; i < 2; i++) {
        int idx = tid + i * 256;
        br[i]  = idx >> 4;
        bc4[i] = (idx & 15) * 4;
    }

    float4 pa[4], pb[2];
    // prologue: load K-tile 0
    #pragma unroll
    for (int i = 0; i < 4; i++) {
        int gr = bm + ar[i];
        pa[i] = (gr < N_NODES) ? *(const float4*)(g_x + (size_t)gr * G_DIM + ac4[i])
                               : make_float4(0.f, 0.f, 0.f, 0.f);
    }
    #pragma unroll
    for (int i = 0; i < 2; i++)
        pb[i] = *(const float4*)(W + (size_t)br[i] * 768 + bn + bc4[i]);

    for (int kt8 = 0; kt8 < 8; kt8++) {
        // ---- store staged tile into fragment-permuted smem
        #pragma unroll
        for (int i = 0; i < 4; i++) {
            float fv[4] = {pa[i].x, pa[i].y, pa[i].z, pa[i].w};
            int mi = ar[i] >> 4, rr = ar[i] & 15;
            #pragma unroll
            for (int j = 0; j < 4; j++) {
                int col = ac4[i] + j;
                int ks = col >> 3, cc = col & 7;
                int lt = (rr & 7) * 4 + (cc & 3);
                int rg = ((rr >> 3) & 1) | ((cc >> 2) << 1);
                Asm[ks][mi][lt][rg] = to_tf32(fv[j]);
            }
        }
        #pragma unroll
        for (int i = 0; i < 2; i++) {
            float fv[4] = {pb[i].x, pb[i].y, pb[i].z, pb[i].w};
            int ks = br[i] >> 3, kk = br[i] & 7;
            #pragma unroll
            for (int j = 0; j < 4; j++) {
                int col = bc4[i] + j;
                int ni = col >> 3, nn = col & 7;
                int lt = nn * 4 + (kk & 3);
                int rg = kk >> 2;
                Bsm[ks][ni][lt][rg] = to_tf32(fv[j]);
            }
        }
        __syncthreads();

        // ---- prefetch next K-tile while tensor cores run
        if (kt8 < 7) {
            int kt = (kt8 + 1) * 32;
            #pragma unroll
            for (int i = 0; i < 4; i++) {
                int gr = bm + ar[i];
                pa[i] = (gr < N_NODES)
                      ? *(const float4*)(g_x + (size_t)gr * G_DIM + kt + ac4[i])
                      : make_float4(0.f, 0.f, 0.f, 0.f);
            }
            #pragma unroll
            for (int i = 0; i < 2; i++)
                pb[i] = *(const float4*)(W + (size_t)(kt + br[i]) * 768 + bn + bc4[i]);
        }

        #pragma unroll
        for (int ks = 0; ks < 4; ks++) {
            uint32_t a[2][4];
            #pragma unroll
            for (int mi = 0; mi < 2; mi++)
                *(uint4*)a[mi] = *(const uint4*)&Asm[ks][wm * 2 + mi][lane][0];
            uint32_t b[4][2];
            #pragma unroll
            for (int ni = 0; ni < 4; ni++)
                *(uint2*)b[ni] = *(const uint2*)&Bsm[ks][wn * 4 + ni][lane][0];
            #pragma unroll
            for (int mi = 0; mi < 2; mi++)
                #pragma unroll
                for (int ni = 0; ni < 4; ni++)
                    mma_tf32(acc[mi][ni], a[mi], b[ni]);
        }
        __syncthreads();
    }

    int third = bn >> 8;
    float* outp = (third == 0) ? g_q : (third == 1) ? g_k : g_v;
    int lc_base = (bn & 255) + wn * 32;
    int gid = lane >> 2, tig = lane & 3;
    #pragma unroll
    for (int mi = 0; mi < 2; mi++) {
        int row0 = bm + wm * 32 + mi * 16 + gid;
        #pragma unroll
        for (int ni = 0; ni < 4; ni++) {
            int col = lc_base + ni * 8 + tig * 2;
            if (row0 < N_NODES)
                *(float2*)&outp[(size_t)row0 * G_DIM + col] =
                    make_float2(acc[mi][ni][0], acc[mi][ni][1]);
            if (row0 + 8 < N_NODES)
                *(float2*)&outp[(size_t)(row0 + 8) * G_DIM + col] =
                    make_float2(acc[mi][ni][2], acc[mi][ni][3]);
        }
    }
}

// ---------------- CSR build ----------------
__global__ void hist_kernel(const int* __restrict__ dst) {
    int e = blockIdx.x * blockDim.x + threadIdx.x;
    if (e < E_EDGES) atomicAdd(&g_deg[dst[e]], 1);
}

// parallel exclusive scan of g_deg -> g_off; also zeroes g_cur
__global__ __launch_bounds__(1024) void scan_kernel() {
    __shared__ int warp_sums[32];
    const int PER = 30;                 // 1024*30 = 30720 >= 30000
    int t = threadIdx.x;
    int lane = t & 31, wid = t >> 5;
    int beg = t * PER;

    int vals[PER];
    int sum = 0;
    #pragma unroll
    for (int i = 0; i < PER; i++) {
        int idx = beg + i;
        int v = (idx < N_NODES) ? g_deg[idx] : 0;
        vals[i] = sum;                  // local exclusive prefix
        sum += v;
    }
    // warp inclusive scan of per-thread sums
    int x = sum;
    #pragma unroll
    for (int o = 1; o < 32; o <<= 1) {
        int y = __shfl_up_sync(0xffffffffu, x, o);
        if (lane >= o) x += y;
    }
    if (lane == 31) warp_sums[wid] = x;
    __syncthreads();
    if (wid == 0) {
        int w = warp_sums[lane];
        #pragma unroll
        for (int o = 1; o < 32; o <<= 1) {
            int y = __shfl_up_sync(0xffffffffu, w, o);
            if (lane >= o) w += y;
        }
        warp_sums[lane] = w;
    }
    __syncthreads();
    int base = x - sum;                 // exclusive within warp
    if (wid > 0) base += warp_sums[wid - 1];
    #pragma unroll
    for (int i = 0; i < PER; i++) {
        int idx = beg + i;
        if (idx < N_NODES) { g_off[idx] = base + vals[i]; g_cur[idx] = 0; }
    }
    if (t == 0) g_off[N_NODES] = E_EDGES;
}

__global__ void scatter_kernel(const int* __restrict__ src, const int* __restrict__ dst) {
    int e = blockIdx.x * blockDim.x + threadIdx.x;
    if (e >= E_EDGES) return;
    int d = dst[e];
    int pos = atomicAdd(&g_cur[d], 1);
    g_csr_src[g_off[d] + pos] = src[e];
}

// ---------------- per-node attention, one warp per dst node (R3 measured-best form) ----
// Logits q*k*2^-4 are tiny -> plain exp == softmax (no running max needed).
__global__ __launch_bounds__(256) void attn_kernel(float* __restrict__ out) {
    int node = (blockIdx.x * blockDim.x + threadIdx.x) >> 5;
    if (node >= N_NODES) return;
    int lane = threadIdx.x & 31;

    const float4* kp = (const float4*)(g_k + (size_t)node * G_DIM);
    float4 k0 = kp[lane * 2];
    float4 k1 = kp[lane * 2 + 1];
    float kk[8] = {k0.x * ATT_SCALE, k0.y * ATT_SCALE, k0.z * ATT_SCALE, k0.w * ATT_SCALE,
                   k1.x * ATT_SCALE, k1.y * ATT_SCALE, k1.z * ATT_SCALE, k1.w * ATT_SCALE};

    float z[8], a[8];
    #pragma unroll
    for (int d = 0; d < 8; d++) { z[d] = 0.f; a[d] = 0.f; }

    int beg = g_off[node], end = g_off[node + 1];
    for (int e = beg; e < end; e++) {
        int sN = g_csr_src[e];
        const float4* qp = (const float4*)(g_q + (size_t)sN * G_DIM);
        const float4* vp = (const float4*)(g_v + (size_t)sN * G_DIM);
        float4 q0 = qp[lane * 2], q1 = qp[lane * 2 + 1];
        float4 v0 = vp[lane * 2], v1 = vp[lane * 2 + 1];
        float qa[8] = {q0.x, q0.y, q0.z, q0.w, q1.x, q1.y, q1.z, q1.w};
        float va[8] = {v0.x, v0.y, v0.z, v0.w, v1.x, v1.y, v1.z, v1.w};
        #pragma unroll
        for (int d = 0; d < 8; d++) {
            float p = __expf(qa[d] * kk[d]);
            z[d] += p;
            a[d] = fmaf(p, va[d], a[d]);
        }
    }

    float res[8];
    #pragma unroll
    for (int d = 0; d < 8; d++) res[d] = (z[d] > 0.f) ? a[d] / z[d] : 0.f;
    float4* op = (float4*)(out + (size_t)node * G_DIM);
    op[lane * 2]     = make_float4(res[0], res[1], res[2], res[3]);
    op[lane * 2 + 1] = make_float4(res[4], res[5], res[6], res[7]);
}

// ---------------- launch ----------------
extern "C" void kernel_launch(void* const* d_in, const int* in_sizes, int n_in,
                              void* d_out, int out_size) {
    const float* s     = (const float*)d_in[0];
    const float* Wqkv  = (const float*)d_in[1];
    const float* gamma = (const float*)d_in[2];
    const float* beta  = (const float*)d_in[3];
    const int*   src   = (const int*)d_in[4];
    const int*   dst   = (const int*)d_in[5];
    float* out = (float*)d_out;

    ln_kernel<<<(N_NODES * 32 + 255) / 256, 256>>>(s, gamma, beta);

    hist_kernel<<<(E_EDGES + 255) / 256, 256>>>(dst);

    dim3 gemm_grid(768 / 64, (N_NODES + 127) / 128);
    qkv_gemm_tf32_kernel<<<gemm_grid, 256>>>(Wqkv);

    scan_kernel<<<1, 1024>>>();
    scatter_kernel<<<(E_EDGES + 255) / 256, 256>>>(src, dst);

    attn_kernel<<<(N_NODES * 32 + 255) / 256, 256>>>(out);
}

// round 8
// speedup vs baseline: 1.3083x; 1.1392x over previous
#include <cuda_runtime.h>
#include <math.h>
#include <stdint.h>

#define N_NODES 30000
#define E_EDGES 480000
#define G_DIM   256
#define ATT_SCALE 0.0625f   /* 256^-0.5 */
#define LN_EPS  1e-5f

// ---------------- device scratch (static allocation only) ----------------
__device__ float g_x[N_NODES * G_DIM];   // normalized input
__device__ float g_q[N_NODES * G_DIM];
__device__ float g_k[N_NODES * G_DIM];
__device__ float g_v[N_NODES * G_DIM];
__device__ int   g_deg[N_NODES];
__device__ int   g_cur[N_NODES];
__device__ int   g_off[N_NODES + 1];
__device__ int   g_csr_src[E_EDGES];
__device__ int   g_bsum[32];

// ---------------- LayerNorm (stats + apply), one warp per row; zeroes g_deg ----------------
__global__ void ln_kernel(const float* __restrict__ s,
                          const float* __restrict__ gamma,
                          const float* __restrict__ beta) {
    int gtid = blockIdx.x * blockDim.x + threadIdx.x;
    if (gtid < N_NODES) g_deg[gtid] = 0;     // fused zero for histogram
    int row = gtid >> 5;
    if (row >= N_NODES) return;
    int lane = threadIdx.x & 31;

    const float4* p = (const float4*)(s + (size_t)row * G_DIM);
    float4 f0 = p[lane];
    float4 f1 = p[lane + 32];
    float sum = f0.x + f0.y + f0.z + f0.w + f1.x + f1.y + f1.z + f1.w;
    float sq  = f0.x*f0.x + f0.y*f0.y + f0.z*f0.z + f0.w*f0.w
              + f1.x*f1.x + f1.y*f1.y + f1.z*f1.z + f1.w*f1.w;
    #pragma unroll
    for (int o = 16; o > 0; o >>= 1) {
        sum += __shfl_xor_sync(0xffffffffu, sum, o);
        sq  += __shfl_xor_sync(0xffffffffu, sq, o);
    }
    float mu = sum * (1.f / G_DIM);
    float rs = rsqrtf(sq * (1.f / G_DIM) - mu * mu + LN_EPS);

    float4 ga = ((const float4*)gamma)[lane];
    float4 gb = ((const float4*)gamma)[lane + 32];
    float4 ba = ((const float4*)beta)[lane];
    float4 bb = ((const float4*)beta)[lane + 32];
    float4 o0, o1;
    o0.x = (f0.x - mu) * rs * ga.x + ba.x;
    o0.y = (f0.y - mu) * rs * ga.y + ba.y;
    o0.z = (f0.z - mu) * rs * ga.z + ba.z;
    o0.w = (f0.w - mu) * rs * ga.w + ba.w;
    o1.x = (f1.x - mu) * rs * gb.x + bb.x;
    o1.y = (f1.y - mu) * rs * gb.y + bb.y;
    o1.z = (f1.z - mu) * rs * gb.z + bb.z;
    o1.w = (f1.w - mu) * rs * gb.w + bb.w;
    float4* op = (float4*)(g_x + (size_t)row * G_DIM);
    op[lane]      = o0;
    op[lane + 32] = o1;
}

// ---------------- tf32 helpers ----------------
__device__ __forceinline__ uint32_t to_tf32(float x) {
    uint32_t t;
    asm("cvt.rna.tf32.f32 %0, %1;" : "=r"(t) : "f"(x));
    return t;
}

__device__ __forceinline__ void mma_tf32(float c[4], const uint32_t a[4], const uint32_t b[2]) {
    asm volatile(
        "mma.sync.aligned.m16n8k8.row.col.f32.tf32.tf32.f32 "
        "{%0,%1,%2,%3}, {%4,%5,%6,%7}, {%8,%9}, {%0,%1,%2,%3};"
        : "+f"(c[0]), "+f"(c[1]), "+f"(c[2]), "+f"(c[3])
        : "r"(a[0]), "r"(a[1]), "r"(a[2]), "r"(a[3]), "r"(b[0]), "r"(b[1]));
}

// ---------------- QKV GEMM (tf32 tensor cores, register-prefetch pipelined) ----------------
__global__ __launch_bounds__(256) void qkv_gemm_tf32_kernel(
    const float* __restrict__ W) {

    __shared__ uint32_t Asm[4][8][32][4];   // 16 KB
    __shared__ uint32_t Bsm[4][8][32][2];   // 8 KB

    int tid  = threadIdx.x;
    int warp = tid >> 5;
    int lane = tid & 31;
    int wm = warp >> 1;
    int wn = warp & 1;
    int bm = blockIdx.y * 128;
    int bn = blockIdx.x * 64;

    float acc[2][4][4];
    #pragma unroll
    for (int mi = 0; mi < 2; mi++)
        #pragma unroll
        for (int ni = 0; ni < 4; ni++)
            #pragma unroll
            for (int r = 0; r < 4; r++) acc[mi][ni][r] = 0.f;

    int ar[4], ac4[4];
    #pragma unroll
    for (int i = 0; i < 4; i++) {
        int idx = tid + i * 256;
        ar[i]  = idx >> 3;
        ac4[i] = (idx & 7) * 4;
    }
    int br[2], bc4[2];
    #pragma unroll
    for (int i = 0; i < 2; i++) {
        int idx = tid + i * 256;
        br[i]  = idx >> 4;
        bc4[i] = (idx & 15) * 4;
    }

    float4 pa[4], pb[2];
    #pragma unroll
    for (int i = 0; i < 4; i++) {
        int gr = bm + ar[i];
        pa[i] = (gr < N_NODES) ? *(const float4*)(g_x + (size_t)gr * G_DIM + ac4[i])
                               : make_float4(0.f, 0.f, 0.f, 0.f);
    }
    #pragma unroll
    for (int i = 0; i < 2; i++)
        pb[i] = *(const float4*)(W + (size_t)br[i] * 768 + bn + bc4[i]);

    for (int kt8 = 0; kt8 < 8; kt8++) {
        #pragma unroll
        for (int i = 0; i < 4; i++) {
            float fv[4] = {pa[i].x, pa[i].y, pa[i].z, pa[i].w};
            int mi = ar[i] >> 4, rr = ar[i] & 15;
            #pragma unroll
            for (int j = 0; j < 4; j++) {
                int col = ac4[i] + j;
                int ks = col >> 3, cc = col & 7;
                int lt = (rr & 7) * 4 + (cc & 3);
                int rg = ((rr >> 3) & 1) | ((cc >> 2) << 1);
                Asm[ks][mi][lt][rg] = to_tf32(fv[j]);
            }
        }
        #pragma unroll
        for (int i = 0; i < 2; i++) {
            float fv[4] = {pb[i].x, pb[i].y, pb[i].z, pb[i].w};
            int ks = br[i] >> 3, kk = br[i] & 7;
            #pragma unroll
            for (int j = 0; j < 4; j++) {
                int col = bc4[i] + j;
                int ni = col >> 3, nn = col & 7;
                int lt = nn * 4 + (kk & 3);
                int rg = kk >> 2;
                Bsm[ks][ni][lt][rg] = to_tf32(fv[j]);
            }
        }
        __syncthreads();

        if (kt8 < 7) {
            int kt = (kt8 + 1) * 32;
            #pragma unroll
            for (int i = 0; i < 4; i++) {
                int gr = bm + ar[i];
                pa[i] = (gr < N_NODES)
                      ? *(const float4*)(g_x + (size_t)gr * G_DIM + kt + ac4[i])
                      : make_float4(0.f, 0.f, 0.f, 0.f);
            }
            #pragma unroll
            for (int i = 0; i < 2; i++)
                pb[i] = *(const float4*)(W + (size_t)(kt + br[i]) * 768 + bn + bc4[i]);
        }

        #pragma unroll
        for (int ks = 0; ks < 4; ks++) {
            uint32_t a[2][4];
            #pragma unroll
            for (int mi = 0; mi < 2; mi++)
                *(uint4*)a[mi] = *(const uint4*)&Asm[ks][wm * 2 + mi][lane][0];
            uint32_t b[4][2];
            #pragma unroll
            for (int ni = 0; ni < 4; ni++)
                *(uint2*)b[ni] = *(const uint2*)&Bsm[ks][wn * 4 + ni][lane][0];
            #pragma unroll
            for (int mi = 0; mi < 2; mi++)
                #pragma unroll
                for (int ni = 0; ni < 4; ni++)
                    mma_tf32(acc[mi][ni], a[mi], b[ni]);
        }
        __syncthreads();
    }

    int third = bn >> 8;
    float* outp = (third == 0) ? g_q : (third == 1) ? g_k : g_v;
    int lc_base = (bn & 255) + wn * 32;
    int gid = lane >> 2, tig = lane & 3;
    #pragma unroll
    for (int mi = 0; mi < 2; mi++) {
        int row0 = bm + wm * 32 + mi * 16 + gid;
        #pragma unroll
        for (int ni = 0; ni < 4; ni++) {
            int col = lc_base + ni * 8 + tig * 2;
            if (row0 < N_NODES)
                *(float2*)&outp[(size_t)row0 * G_DIM + col] =
                    make_float2(acc[mi][ni][0], acc[mi][ni][1]);
            if (row0 + 8 < N_NODES)
                *(float2*)&outp[(size_t)(row0 + 8) * G_DIM + col] =
                    make_float2(acc[mi][ni][2], acc[mi][ni][3]);
        }
    }
}

// ---------------- CSR build ----------------
__global__ void hist_kernel(const int* __restrict__ dst) {
    int e = blockIdx.x * blockDim.x + threadIdx.x;
    if (e < E_EDGES) atomicAdd(&g_deg[dst[e]], 1);
}

// multi-block scan: phase1 = per-block exclusive scan (30 blocks x 1024)
__global__ __launch_bounds__(1024) void scan_phase1() {
    __shared__ int ws[32];
    int t = threadIdx.x;
    int lane = t & 31, wid = t >> 5;
    int idx = blockIdx.x * 1024 + t;
    int v = (idx < N_NODES) ? g_deg[idx] : 0;

    int x = v;
    #pragma unroll
    for (int o = 1; o < 32; o <<= 1) {
        int y = __shfl_up_sync(0xffffffffu, x, o);
        if (lane >= o) x += y;
    }
    if (lane == 31) ws[wid] = x;
    __syncthreads();
    if (wid == 0) {
        int w = ws[lane];
        #pragma unroll
        for (int o = 1; o < 32; o <<= 1) {
            int y = __shfl_up_sync(0xffffffffu, w, o);
            if (lane >= o) w += y;
        }
        ws[lane] = w;
    }
    __syncthreads();
    int ex = x - v + ((wid > 0) ? ws[wid - 1] : 0);
    if (idx < N_NODES) { g_off[idx] = ex; g_cur[idx] = 0; }
    if (t == 1023) g_bsum[blockIdx.x] = ex + v;
}

// phase2: exclusive scan of 30 block sums (one warp)
__global__ void scan_phase2() {
    int t = threadIdx.x;   // 32 threads
    int v = (t < 30) ? g_bsum[t] : 0;
    int x = v;
    #pragma unroll
    for (int o = 1; o < 32; o <<= 1) {
        int y = __shfl_up_sync(0xffffffffu, x, o);
        if (t >= o) x += y;
    }
    g_bsum[t] = x - v;
}

// phase3: add block bases
__global__ __launch_bounds__(1024) void scan_phase3() {
    int idx = blockIdx.x * 1024 + threadIdx.x;
    if (idx < N_NODES) g_off[idx] += g_bsum[blockIdx.x];
    if (idx == 0) g_off[N_NODES] = E_EDGES;
}

__global__ void scatter_kernel(const int* __restrict__ src, const int* __restrict__ dst) {
    int e = blockIdx.x * blockDim.x + threadIdx.x;
    if (e >= E_EDGES) return;
    int d = dst[e];
    int pos = atomicAdd(&g_cur[d], 1);
    g_csr_src[g_off[d] + pos] = src[e];
}

// ---------------- per-node attention: 64 threads (2 warps) per dst node ----------------
// Each thread owns one float4 of dims (64 x 4 = 256); all dims independent.
// Logits q*k*2^-4 are tiny -> plain exp == softmax (no running max needed).
__global__ __launch_bounds__(256) void attn_kernel(float* __restrict__ out) {
    int gtid = blockIdx.x * blockDim.x + threadIdx.x;
    int node = gtid >> 6;
    if (node >= N_NODES) return;
    int doff = gtid & 63;     // float4 index within the 256-dim row

    float4 kv = ((const float4*)(g_k + (size_t)node * G_DIM))[doff];
    kv.x *= ATT_SCALE; kv.y *= ATT_SCALE; kv.z *= ATT_SCALE; kv.w *= ATT_SCALE;

    float4 z = make_float4(0.f, 0.f, 0.f, 0.f);
    float4 a = make_float4(0.f, 0.f, 0.f, 0.f);

    int e   = g_off[node];
    int end = g_off[node + 1];

    for (; e + 2 <= end; e += 2) {
        int s0 = g_csr_src[e];
        int s1 = g_csr_src[e + 1];
        float4 q0 = ((const float4*)(g_q + (size_t)s0 * G_DIM))[doff];
        float4 v0 = ((const float4*)(g_v + (size_t)s0 * G_DIM))[doff];
        float4 q1 = ((const float4*)(g_q + (size_t)s1 * G_DIM))[doff];
        float4 v1 = ((const float4*)(g_v + (size_t)s1 * G_DIM))[doff];

        float p;
        p = __expf(q0.x * kv.x); z.x += p; a.x = fmaf(p, v0.x, a.x);
        p = __expf(q0.y * kv.y); z.y += p; a.y = fmaf(p, v0.y, a.y);
        p = __expf(q0.z * kv.z); z.z += p; a.z = fmaf(p, v0.z, a.z);
        p = __expf(q0.w * kv.w); z.w += p; a.w = fmaf(p, v0.w, a.w);
        p = __expf(q1.x * kv.x); z.x += p; a.x = fmaf(p, v1.x, a.x);
        p = __expf(q1.y * kv.y); z.y += p; a.y = fmaf(p, v1.y, a.y);
        p = __expf(q1.z * kv.z); z.z += p; a.z = fmaf(p, v1.z, a.z);
        p = __expf(q1.w * kv.w); z.w += p; a.w = fmaf(p, v1.w, a.w);
    }
    for (; e < end; e++) {
        int s0 = g_csr_src[e];
        float4 q0 = ((const float4*)(g_q + (size_t)s0 * G_DIM))[doff];
        float4 v0 = ((const float4*)(g_v + (size_t)s0 * G_DIM))[doff];
        float p;
        p = __expf(q0.x * kv.x); z.x += p; a.x = fmaf(p, v0.x, a.x);
        p = __expf(q0.y * kv.y); z.y += p; a.y = fmaf(p, v0.y, a.y);
        p = __expf(q0.z * kv.z); z.z += p; a.z = fmaf(p, v0.z, a.z);
        p = __expf(q0.w * kv.w); z.w += p; a.w = fmaf(p, v0.w, a.w);
    }

    float4 r;
    r.x = (z.x > 0.f) ? a.x / z.x : 0.f;
    r.y = (z.y > 0.f) ? a.y / z.y : 0.f;
    r.z = (z.z > 0.f) ? a.z / z.z : 0.f;
    r.w = (z.w > 0.f) ? a.w / z.w : 0.f;
    ((float4*)(out + (size_t)node * G_DIM))[doff] = r;
}

// ---------------- launch ----------------
extern "C" void kernel_launch(void* const* d_in, const int* in_sizes, int n_in,
                              void* d_out, int out_size) {
    const float* s     = (const float*)d_in[0];
    const float* Wqkv  = (const float*)d_in[1];
    const float* gamma = (const float*)d_in[2];
    const float* beta  = (const float*)d_in[3];
    const int*   src   = (const int*)d_in[4];
    const int*   dst   = (const int*)d_in[5];
    float* out = (float*)d_out;

    ln_kernel<<<(N_NODES * 32 + 255) / 256, 256>>>(s, gamma, beta);

    hist_kernel<<<(E_EDGES + 255) / 256, 256>>>(dst);

    dim3 gemm_grid(768 / 64, (N_NODES + 127) / 128);
    qkv_gemm_tf32_kernel<<<gemm_grid, 256>>>(Wqkv);

    const int SCAN_BLOCKS = (N_NODES + 1023) / 1024;   // 30
    scan_phase1<<<SCAN_BLOCKS, 1024>>>();
    scan_phase2<<<1, 32>>>();
    scan_phase3<<<SCAN_BLOCKS, 1024>>>();

    scatter_kernel<<<(E_EDGES + 255) / 256, 256>>>(src, dst);

    // 64 threads per node
    attn_kernel<<<(N_NODES * 64 + 255) / 256, 256>>>(out);
}

// round 9
// speedup vs baseline: 1.3334x; 1.0192x over previous
#include <cuda_runtime.h>
#include <math.h>
#include <stdint.h>

#define N_NODES 30000
#define E_EDGES 480000
#define G_DIM   256
#define ATT_SCALE 0.0625f   /* 256^-0.5 */
#define LOG2E   1.4426950408889634f
#define LN_EPS  1e-5f

// ---------------- device scratch (static allocation only) ----------------
__device__ float g_x[N_NODES * G_DIM];   // normalized input
__device__ float g_q[N_NODES * G_DIM];
__device__ float g_k[N_NODES * G_DIM];
__device__ float g_v[N_NODES * G_DIM];
__device__ int   g_deg[N_NODES];
__device__ int   g_cur[N_NODES];
__device__ int   g_off[N_NODES + 1];
__device__ int   g_csr_src[E_EDGES];
__device__ int   g_bsum[32];

// ---------------- LayerNorm (stats + apply), one warp per row; zeroes g_deg ----------------
__global__ void ln_kernel(const float* __restrict__ s,
                          const float* __restrict__ gamma,
                          const float* __restrict__ beta) {
    int gtid = blockIdx.x * blockDim.x + threadIdx.x;
    if (gtid < N_NODES) g_deg[gtid] = 0;     // fused zero for histogram
    int row = gtid >> 5;
    if (row >= N_NODES) return;
    int lane = threadIdx.x & 31;

    const float4* p = (const float4*)(s + (size_t)row * G_DIM);
    float4 f0 = p[lane];
    float4 f1 = p[lane + 32];
    float sum = f0.x + f0.y + f0.z + f0.w + f1.x + f1.y + f1.z + f1.w;
    float sq  = f0.x*f0.x + f0.y*f0.y + f0.z*f0.z + f0.w*f0.w
              + f1.x*f1.x + f1.y*f1.y + f1.z*f1.z + f1.w*f1.w;
    #pragma unroll
    for (int o = 16; o > 0; o >>= 1) {
        sum += __shfl_xor_sync(0xffffffffu, sum, o);
        sq  += __shfl_xor_sync(0xffffffffu, sq, o);
    }
    float mu = sum * (1.f / G_DIM);
    float rs = rsqrtf(sq * (1.f / G_DIM) - mu * mu + LN_EPS);

    float4 ga = ((const float4*)gamma)[lane];
    float4 gb = ((const float4*)gamma)[lane + 32];
    float4 ba = ((const float4*)beta)[lane];
    float4 bb = ((const float4*)beta)[lane + 32];
    float4 o0, o1;
    o0.x = (f0.x - mu) * rs * ga.x + ba.x;
    o0.y = (f0.y - mu) * rs * ga.y + ba.y;
    o0.z = (f0.z - mu) * rs * ga.z + ba.z;
    o0.w = (f0.w - mu) * rs * ga.w + ba.w;
    o1.x = (f1.x - mu) * rs * gb.x + bb.x;
    o1.y = (f1.y - mu) * rs * gb.y + bb.y;
    o1.z = (f1.z - mu) * rs * gb.z + bb.z;
    o1.w = (f1.w - mu) * rs * gb.w + bb.w;
    float4* op = (float4*)(g_x + (size_t)row * G_DIM);
    op[lane]      = o0;
    op[lane + 32] = o1;
}

// ---------------- tf32 helpers ----------------
__device__ __forceinline__ uint32_t to_tf32(float x) {
    uint32_t t;
    asm("cvt.rna.tf32.f32 %0, %1;" : "=r"(t) : "f"(x));
    return t;
}

__device__ __forceinline__ void mma_tf32(float c[4], const uint32_t a[4], const uint32_t b[2]) {
    asm volatile(
        "mma.sync.aligned.m16n8k8.row.col.f32.tf32.tf32.f32 "
        "{%0,%1,%2,%3}, {%4,%5,%6,%7}, {%8,%9}, {%0,%1,%2,%3};"
        : "+f"(c[0]), "+f"(c[1]), "+f"(c[2]), "+f"(c[3])
        : "r"(a[0]), "r"(a[1]), "r"(a[2]), "r"(a[3]), "r"(b[0]), "r"(b[1]));
}

// ---------------- QKV GEMM (tf32, double-buffered smem, 1 sync/K-tile) ----------------
// C[N,768] = X[N,256] @ W[256,768]; block tile 128x64, K-chunk 32, 8 warps (4Mx2N).
__global__ __launch_bounds__(256) void qkv_gemm_tf32_kernel(
    const float* __restrict__ W) {

    __shared__ uint32_t Asm[2][4][8][32][4];   // 2 x 16 KB
    __shared__ uint32_t Bsm[2][4][8][32][2];   // 2 x  8 KB  (total 48 KB)

    int tid  = threadIdx.x;
    int warp = tid >> 5;
    int lane = tid & 31;
    int wm = warp >> 1;
    int wn = warp & 1;
    int bm = blockIdx.y * 128;
    int bn = blockIdx.x * 64;

    float acc[2][4][4];
    #pragma unroll
    for (int mi = 0; mi < 2; mi++)
        #pragma unroll
        for (int ni = 0; ni < 4; ni++)
            #pragma unroll
            for (int r = 0; r < 4; r++) acc[mi][ni][r] = 0.f;

    int ar[4], ac4[4];
    #pragma unroll
    for (int i = 0; i < 4; i++) {
        int idx = tid + i * 256;
        ar[i]  = idx >> 3;
        ac4[i] = (idx & 7) * 4;
    }
    int br[2], bc4[2];
    #pragma unroll
    for (int i = 0; i < 2; i++) {
        int idx = tid + i * 256;
        br[i]  = idx >> 4;
        bc4[i] = (idx & 15) * 4;
    }

    float4 pa[4], pb[2];
    // prologue: load + stage K-tile 0 into buffer 0
    #pragma unroll
    for (int i = 0; i < 4; i++) {
        int gr = bm + ar[i];
        pa[i] = (gr < N_NODES) ? *(const float4*)(g_x + (size_t)gr * G_DIM + ac4[i])
                               : make_float4(0.f, 0.f, 0.f, 0.f);
    }
    #pragma unroll
    for (int i = 0; i < 2; i++)
        pb[i] = *(const float4*)(W + (size_t)br[i] * 768 + bn + bc4[i]);

    #pragma unroll
    for (int i = 0; i < 4; i++) {
        float fv[4] = {pa[i].x, pa[i].y, pa[i].z, pa[i].w};
        int mi = ar[i] >> 4, rr = ar[i] & 15;
        #pragma unroll
        for (int j = 0; j < 4; j++) {
            int col = ac4[i] + j;
            int ks = col >> 3, cc = col & 7;
            int lt = (rr & 7) * 4 + (cc & 3);
            int rg = ((rr >> 3) & 1) | ((cc >> 2) << 1);
            Asm[0][ks][mi][lt][rg] = to_tf32(fv[j]);
        }
    }
    #pragma unroll
    for (int i = 0; i < 2; i++) {
        float fv[4] = {pb[i].x, pb[i].y, pb[i].z, pb[i].w};
        int ks = br[i] >> 3, kk = br[i] & 7;
        #pragma unroll
        for (int j = 0; j < 4; j++) {
            int col = bc4[i] + j;
            int ni = col >> 3, nn = col & 7;
            int lt = nn * 4 + (kk & 3);
            int rg = kk >> 2;
            Bsm[0][ks][ni][lt][rg] = to_tf32(fv[j]);
        }
    }
    __syncthreads();

    for (int kt8 = 0; kt8 < 8; kt8++) {
        int cur = kt8 & 1;
        // ---- prefetch next K-tile from global (long-latency, overlaps compute)
        if (kt8 < 7) {
            int kt = (kt8 + 1) * 32;
            #pragma unroll
            for (int i = 0; i < 4; i++) {
                int gr = bm + ar[i];
                pa[i] = (gr < N_NODES)
                      ? *(const float4*)(g_x + (size_t)gr * G_DIM + kt + ac4[i])
                      : make_float4(0.f, 0.f, 0.f, 0.f);
            }
            #pragma unroll
            for (int i = 0; i < 2; i++)
                pb[i] = *(const float4*)(W + (size_t)(kt + br[i]) * 768 + bn + bc4[i]);
        }

        // ---- compute from current buffer
        #pragma unroll
        for (int ks = 0; ks < 4; ks++) {
            uint32_t a[2][4];
            #pragma unroll
            for (int mi = 0; mi < 2; mi++)
                *(uint4*)a[mi] = *(const uint4*)&Asm[cur][ks][wm * 2 + mi][lane][0];
            uint32_t b[4][2];
            #pragma unroll
            for (int ni = 0; ni < 4; ni++)
                *(uint2*)b[ni] = *(const uint2*)&Bsm[cur][ks][wn * 4 + ni][lane][0];
            #pragma unroll
            for (int mi = 0; mi < 2; mi++)
                #pragma unroll
                for (int ni = 0; ni < 4; ni++)
                    mma_tf32(acc[mi][ni], a[mi], b[ni]);
        }

        // ---- stage next tile into the other buffer; single sync
        if (kt8 < 7) {
            int nxt = cur ^ 1;
            #pragma unroll
            for (int i = 0; i < 4; i++) {
                float fv[4] = {pa[i].x, pa[i].y, pa[i].z, pa[i].w};
                int mi = ar[i] >> 4, rr = ar[i] & 15;
                #pragma unroll
                for (int j = 0; j < 4; j++) {
                    int col = ac4[i] + j;
                    int ks = col >> 3, cc = col & 7;
                    int lt = (rr & 7) * 4 + (cc & 3);
                    int rg = ((rr >> 3) & 1) | ((cc >> 2) << 1);
                    Asm[nxt][ks][mi][lt][rg] = to_tf32(fv[j]);
                }
            }
            #pragma unroll
            for (int i = 0; i < 2; i++) {
                float fv[4] = {pb[i].x, pb[i].y, pb[i].z, pb[i].w};
                int ks = br[i] >> 3, kk = br[i] & 7;
                #pragma unroll
                for (int j = 0; j < 4; j++) {
                    int col = bc4[i] + j;
                    int ni = col >> 3, nn = col & 7;
                    int lt = nn * 4 + (kk & 3);
                    int rg = kk >> 2;
                    Bsm[nxt][ks][ni][lt][rg] = to_tf32(fv[j]);
                }
            }
            __syncthreads();
        }
    }

    int third = bn >> 8;
    float* outp = (third == 0) ? g_q : (third == 1) ? g_k : g_v;
    int lc_base = (bn & 255) + wn * 32;
    int gid = lane >> 2, tig = lane & 3;
    #pragma unroll
    for (int mi = 0; mi < 2; mi++) {
        int row0 = bm + wm * 32 + mi * 16 + gid;
        #pragma unroll
        for (int ni = 0; ni < 4; ni++) {
            int col = lc_base + ni * 8 + tig * 2;
            if (row0 < N_NODES)
                *(float2*)&outp[(size_t)row0 * G_DIM + col] =
                    make_float2(acc[mi][ni][0], acc[mi][ni][1]);
            if (row0 + 8 < N_NODES)
                *(float2*)&outp[(size_t)(row0 + 8) * G_DIM + col] =
                    make_float2(acc[mi][ni][2], acc[mi][ni][3]);
        }
    }
}

// ---------------- CSR build ----------------
__global__ void hist_kernel(const int* __restrict__ dst) {
    int e = blockIdx.x * blockDim.x + threadIdx.x;
    if (e < E_EDGES) atomicAdd(&g_deg[dst[e]], 1);
}

__global__ __launch_bounds__(1024) void scan_phase1() {
    __shared__ int ws[32];
    int t = threadIdx.x;
    int lane = t & 31, wid = t >> 5;
    int idx = blockIdx.x * 1024 + t;
    int v = (idx < N_NODES) ? g_deg[idx] : 0;

    int x = v;
    #pragma unroll
    for (int o = 1; o < 32; o <<= 1) {
        int y = __shfl_up_sync(0xffffffffu, x, o);
        if (lane >= o) x += y;
    }
    if (lane == 31) ws[wid] = x;
    __syncthreads();
    if (wid == 0) {
        int w = ws[lane];
        #pragma unroll
        for (int o = 1; o < 32; o <<= 1) {
            int y = __shfl_up_sync(0xffffffffu, w, o);
            if (lane >= o) w += y;
        }
        ws[lane] = w;
    }
    __syncthreads();
    int ex = x - v + ((wid > 0) ? ws[wid - 1] : 0);
    if (idx < N_NODES) { g_off[idx] = ex; g_cur[idx] = 0; }
    if (t == 1023) g_bsum[blockIdx.x] = ex + v;
}

__global__ void scan_phase2() {
    int t = threadIdx.x;   // 32 threads
    int v = (t < 30) ? g_bsum[t] : 0;
    int x = v;
    #pragma unroll
    for (int o = 1; o < 32; o <<= 1) {
        int y = __shfl_up_sync(0xffffffffu, x, o);
        if (t >= o) x += y;
    }
    g_bsum[t] = x - v;
}

__global__ __launch_bounds__(1024) void scan_phase3() {
    int idx = blockIdx.x * 1024 + threadIdx.x;
    if (idx < N_NODES) g_off[idx] += g_bsum[blockIdx.x];
    if (idx == 0) g_off[N_NODES] = E_EDGES;
}

__global__ void scatter_kernel(const int* __restrict__ src, const int* __restrict__ dst) {
    int e = blockIdx.x * blockDim.x + threadIdx.x;
    if (e >= E_EDGES) return;
    int d = dst[e];
    int pos = atomicAdd(&g_cur[d], 1);
    g_csr_src[g_off[d] + pos] = src[e];
}

// ---------------- per-node attention: 64 threads (2 warps) per dst node ----------------
// Each thread owns one float4 of dims. Logits q*k*2^-4 are tiny -> plain exp ==
// softmax. log2(e) folded into the cached k so exp is a single MUFU.EX2.
__device__ __forceinline__ float ex2f(float x) {
    float r;
    asm("ex2.approx.ftz.f32 %0, %1;" : "=f"(r) : "f"(x));
    return r;
}

__global__ __launch_bounds__(256) void attn_kernel(float* __restrict__ out) {
    int gtid = blockIdx.x * blockDim.x + threadIdx.x;
    int node = gtid >> 6;
    if (node >= N_NODES) return;
    int doff = gtid & 63;     // float4 index within the 256-dim row

    const float KS = ATT_SCALE * LOG2E;
    float4 kv = ((const float4*)(g_k + (size_t)node * G_DIM))[doff];
    kv.x *= KS; kv.y *= KS; kv.z *= KS; kv.w *= KS;

    float4 z = make_float4(0.f, 0.f, 0.f, 0.f);
    float4 a = make_float4(0.f, 0.f, 0.f, 0.f);

    int e   = g_off[node];
    int end = g_off[node + 1];

    for (; e + 2 <= end; e += 2) {
        int s0 = g_csr_src[e];
        int s1 = g_csr_src[e + 1];
        float4 q0 = ((const float4*)(g_q + (size_t)s0 * G_DIM))[doff];
        float4 v0 = ((const float4*)(g_v + (size_t)s0 * G_DIM))[doff];
        float4 q1 = ((const float4*)(g_q + (size_t)s1 * G_DIM))[doff];
        float4 v1 = ((const float4*)(g_v + (size_t)s1 * G_DIM))[doff];

        float p;
        p = ex2f(q0.x * kv.x); z.x += p; a.x = fmaf(p, v0.x, a.x);
        p = ex2f(q0.y * kv.y); z.y += p; a.y = fmaf(p, v0.y, a.y);
        p = ex2f(q0.z * kv.z); z.z += p; a.z = fmaf(p, v0.z, a.z);
        p = ex2f(q0.w * kv.w); z.w += p; a.w = fmaf(p, v0.w, a.w);
        p = ex2f(q1.x * kv.x); z.x += p; a.x = fmaf(p, v1.x, a.x);
        p = ex2f(q1.y * kv.y); z.y += p; a.y = fmaf(p, v1.y, a.y);
        p = ex2f(q1.z * kv.z); z.z += p; a.z = fmaf(p, v1.z, a.z);
        p = ex2f(q1.w * kv.w); z.w += p; a.w = fmaf(p, v1.w, a.w);
    }
    for (; e < end; e++) {
        int s0 = g_csr_src[e];
        float4 q0 = ((const float4*)(g_q + (size_t)s0 * G_DIM))[doff];
        float4 v0 = ((const float4*)(g_v + (size_t)s0 * G_DIM))[doff];
        float p;
        p = ex2f(q0.x * kv.x); z.x += p; a.x = fmaf(p, v0.x, a.x);
        p = ex2f(q0.y * kv.y); z.y += p; a.y = fmaf(p, v0.y, a.y);
        p = ex2f(q0.z * kv.z); z.z += p; a.z = fmaf(p, v0.z, a.z);
        p = ex2f(q0.w * kv.w); z.w += p; a.w = fmaf(p, v0.w, a.w);
    }

    float4 r;
    r.x = (z.x > 0.f) ? a.x / z.x : 0.f;
    r.y = (z.y > 0.f) ? a.y / z.y : 0.f;
    r.z = (z.z > 0.f) ? a.z / z.z : 0.f;
    r.w = (z.w > 0.f) ? a.w / z.w : 0.f;
    ((float4*)(out + (size_t)node * G_DIM))[doff] = r;
}

// ---------------- launch ----------------
extern "C" void kernel_launch(void* const* d_in, const int* in_sizes, int n_in,
                              void* d_out, int out_size) {
    const float* s     = (const float*)d_in[0];
    const float* Wqkv  = (const float*)d_in[1];
    const float* gamma = (const float*)d_in[2];
    const float* beta  = (const float*)d_in[3];
    const int*   src   = (const int*)d_in[4];
    const int*   dst   = (const int*)d_in[5];
    float* out = (float*)d_out;

    ln_kernel<<<(N_NODES * 32 + 255) / 256, 256>>>(s, gamma, beta);

    hist_kernel<<<(E_EDGES + 255) / 256, 256>>>(dst);

    dim3 gemm_grid(768 / 64, (N_NODES + 127) / 128);
    qkv_gemm_tf32_kernel<<<gemm_grid, 256>>>(Wqkv);

    const int SCAN_BLOCKS = (N_NODES + 1023) / 1024;   // 30
    scan_phase1<<<SCAN_BLOCKS, 1024>>>();
    scan_phase2<<<1, 32>>>();
    scan_phase3<<<SCAN_BLOCKS, 1024>>>();

    scatter_kernel<<<(E_EDGES + 255) / 256, 256>>>(src, dst);

    attn_kernel<<<(N_NODES * 64 + 255) / 256, 256>>>(out);
}